// round 10
// baseline (speedup 1.0000x reference)
#include <cuda_runtime.h>

// ---------------- problem constants ----------------
#define NENVS 4096
#define SEQL  128
#define LATD  64
#define EMBD  256
#define HIDD  1024
#define G3    3072          // 3 * HIDD
#define H2    512           // HIDD / 2
#define MENV  32            // envs per CTA
#define NCTA  (NENVS / MENV)
#define NTHR  256

#define OUTS_ELEMS (NENVS * SEQL * 2)

// ---------------- shared memory layout (floats) ----------------
#define SM_H   0                         // h       [32][1024]      32768
#define SM_U   (MENV * HIDD)             // union region base
#define SM_X2  SM_U                      // x2      [32][256]        8192
#define SM_X1  (SM_U + MENV * EMBD)      // x1      [32][32]         1024
#define SM_Z   (SM_X1 + MENV * 32)       // z_t     [32][64]         2048
#define SM_O1  SM_U                      // o1      [32][516] (overlays x1/x2/z)
#define O1STR  516                       // padded stride (bank-conflict avoidance)
#define SM_ST  (SM_U + MENV * O1STR)     // state   [32][2]
#define SM_TOT (SM_ST + MENV * 2)
#define SMEM_BYTES (SM_TOT * 4)

typedef unsigned long long ull;

// h_new scratch: can't overwrite smem h while it is still the K-operand
__device__ float g_hnew[NENVS * HIDD];

// ---------------- f32x2 helpers (PTX-only FFMA2 path on sm_103a) ----------------
__device__ __forceinline__ ull pk2(float lo, float hi) {
    ull r; asm("mov.b64 %0, {%1,%2};" : "=l"(r) : "f"(lo), "f"(hi)); return r;
}
__device__ __forceinline__ float2 upk2(ull v) {
    float2 f; asm("mov.b64 {%0,%1}, %2;" : "=f"(f.x), "=f"(f.y) : "l"(v)); return f;
}
#define FMA2(acc, aa, bb) \
    asm("fma.rn.f32x2 %0, %1, %2, %0;" : "+l"(acc) : "l"(aa), "l"(bb))

__device__ __forceinline__ float sigmf(float x) { return 1.0f / (1.0f + expf(-x)); }
__device__ __forceinline__ float gru1(float rr, float zz, float ni, float nh, float hold) {
    float r = sigmf(rr);
    float u = sigmf(zz);
    float n = tanhf(ni + r * nh);
    return (1.0f - u) * n + u * hold;
}

__global__ __launch_bounds__(NTHR, 1)
void gru_decoder_kernel(
    const float* __restrict__ z,   const float* __restrict__ h0,
    const float* __restrict__ w1,  const float* __restrict__ b1,
    const float* __restrict__ w2,  const float* __restrict__ b2,
    const float* __restrict__ wih, const float* __restrict__ bih,
    const float* __restrict__ whh, const float* __restrict__ bhh,
    const float* __restrict__ w3,  const float* __restrict__ b3,
    const float* __restrict__ w4,  const float* __restrict__ b4,
    float* __restrict__ out, int write_h)
{
    extern __shared__ float sm[];
    const int tid  = threadIdx.x;
    const int env0 = blockIdx.x * MENV;

    float* hs  = sm + SM_H;
    float* x2s = sm + SM_X2;
    float* x1s = sm + SM_X1;
    float* zs  = sm + SM_Z;
    float* o1s = sm + SM_O1;
    float* sts = sm + SM_ST;

    // initial hidden state: this CTA's 32 env rows are contiguous in h0
    {
        const float4* src = (const float4*)(h0 + (size_t)env0 * HIDD);
        float4* dst = (float4*)hs;
        for (int i = tid; i < MENV * HIDD / 4; i += NTHR) dst[i] = src[i];
    }
    if (tid < MENV * 2) sts[tid] = -2.0f;   // initial fake state/action
    __syncthreads();

    // gate/o1-loop tiling: 64 col-threads x 2 cols, 4 env-groups x 8 envs
    const int ct  = tid & 63;
    const int mt  = tid >> 6;
    const int e0l = mt * 8;

    const ull* wihu = (const ull*)wih;   // ull i <-> floats 2i, 2i+1
    const ull* whhu = (const ull*)whh;
    const ull* w3u  = (const ull*)w3;

    for (int t = 0; t < SEQL; ++t) {
        // ---- stage z_t into smem ----
        for (int i = tid; i < MENV * LATD; i += NTHR) {
            int e = i >> 6, d = i & 63;
            zs[i] = z[((size_t)(env0 + e) * SEQL + t) * LATD + d];
        }
        __syncthreads();

        // ---- x1 = relu([state | z_t] @ w1 + b1)  (K=66, N=32) ----
        for (int o = tid; o < MENV * 32; o += NTHR) {
            int e = o >> 5, c = o & 31;
            float acc = b1[c]
                      + sts[e * 2 + 0] * w1[c]
                      + sts[e * 2 + 1] * w1[32 + c];
            #pragma unroll 8
            for (int k = 0; k < LATD; ++k)
                acc = fmaf(zs[e * LATD + k], w1[(2 + k) * 32 + c], acc);
            x1s[e * 32 + c] = fmaxf(acc, 0.0f);
        }
        __syncthreads();

        // ---- x2 = relu(x1 @ w2 + b2)  (one column, 32 envs per thread) ----
        {
            const int c = tid;                   // EMBD == NTHR == 256
            float acc[MENV];
            #pragma unroll
            for (int e = 0; e < MENV; ++e) acc[e] = b2[c];
            #pragma unroll 4
            for (int k = 0; k < 32; ++k) {
                float b = __ldg(w2 + k * EMBD + c);
                #pragma unroll
                for (int e = 0; e < MENV; ++e)
                    acc[e] = fmaf(x1s[e * 32 + k], b, acc[e]);
            }
            #pragma unroll
            for (int e = 0; e < MENV; ++e)
                x2s[e * EMBD + c] = fmaxf(acc[e], 0.0f);
        }
        __syncthreads();

        // ---- fused GRU gates: per 128-col block compute
        //      (i_r+h_r), (i_z+h_z), i_n, h_n  then combine -> h_new ----
        for (int nb = 0; nb < HIDD; nb += 128) {
            const int cb = nb + ct * 2;            // 2 cols per thread
            ull aR[8], aZ[8], aNi[8], aNh[8];
            {
                ull r0 = pk2(bih[cb] + bhh[cb], bih[cb + 1] + bhh[cb + 1]);
                ull z0 = pk2(bih[HIDD + cb] + bhh[HIDD + cb],
                             bih[HIDD + cb + 1] + bhh[HIDD + cb + 1]);
                ull i0 = pk2(bih[2 * HIDD + cb], bih[2 * HIDD + cb + 1]);
                ull n0 = pk2(bhh[2 * HIDD + cb], bhh[2 * HIDD + cb + 1]);
                #pragma unroll
                for (int i = 0; i < 8; ++i) {
                    aR[i] = r0; aZ[i] = z0; aNi[i] = i0; aNh[i] = n0;
                }
            }
            // x2 @ wih   (K = 256), k-quads with LDS.128 activation staging
            {
                const ull* pr = wihu + (cb >> 1);
                const ull* pz = wihu + ((HIDD + cb) >> 1);
                const ull* pn = wihu + ((2 * HIDD + cb) >> 1);
                for (int k0 = 0; k0 < EMBD; k0 += 4) {
                    float4 xv[8];
                    #pragma unroll
                    for (int e = 0; e < 8; ++e)
                        xv[e] = *(const float4*)(x2s + (e0l + e) * EMBD + k0);
                    #pragma unroll
                    for (int kk = 0; kk < 4; ++kk) {
                        ull br = __ldg(pr); pr += G3 / 2;
                        ull bz = __ldg(pz); pz += G3 / 2;
                        ull bn = __ldg(pn); pn += G3 / 2;
                        #pragma unroll
                        for (int e = 0; e < 8; ++e) {
                            float a = kk == 0 ? xv[e].x : kk == 1 ? xv[e].y
                                    : kk == 2 ? xv[e].z : xv[e].w;
                            ull aa = pk2(a, a);
                            FMA2(aR[e],  aa, br);
                            FMA2(aZ[e],  aa, bz);
                            FMA2(aNi[e], aa, bn);
                        }
                    }
                }
            }
            // h @ whh   (K = 1024)
            {
                const ull* pr = whhu + (cb >> 1);
                const ull* pz = whhu + ((HIDD + cb) >> 1);
                const ull* pn = whhu + ((2 * HIDD + cb) >> 1);
                for (int k0 = 0; k0 < HIDD; k0 += 4) {
                    float4 hv[8];
                    #pragma unroll
                    for (int e = 0; e < 8; ++e)
                        hv[e] = *(const float4*)(hs + (e0l + e) * HIDD + k0);
                    #pragma unroll
                    for (int kk = 0; kk < 4; ++kk) {
                        ull br = __ldg(pr); pr += G3 / 2;
                        ull bz = __ldg(pz); pz += G3 / 2;
                        ull bn = __ldg(pn); pn += G3 / 2;
                        #pragma unroll
                        for (int e = 0; e < 8; ++e) {
                            float a = kk == 0 ? hv[e].x : kk == 1 ? hv[e].y
                                    : kk == 2 ? hv[e].z : hv[e].w;
                            ull aa = pk2(a, a);
                            FMA2(aR[e],  aa, br);
                            FMA2(aZ[e],  aa, bz);
                            FMA2(aNh[e], aa, bn);
                        }
                    }
                }
            }
            // combine -> h_new (to global scratch; smem h still the K-operand)
            #pragma unroll
            for (int e = 0; e < 8; ++e) {
                float2 R = upk2(aR[e]);
                float2 Z = upk2(aZ[e]);
                float2 I = upk2(aNi[e]);
                float2 N = upk2(aNh[e]);
                const float* hrow = hs + (e0l + e) * HIDD + cb;
                float2 hv;
                hv.x = gru1(R.x, Z.x, I.x, N.x, hrow[0]);
                hv.y = gru1(R.y, Z.y, I.y, N.y, hrow[1]);
                *(float2*)(g_hnew + (size_t)(env0 + e0l + e) * HIDD + cb) = hv;
            }
        }
        __syncthreads();

        // ---- h <- h_new ----
        {
            const float4* src = (const float4*)(g_hnew + (size_t)env0 * HIDD);
            float4* dst = (float4*)hs;
            for (int i = tid; i < MENV * HIDD / 4; i += NTHR) dst[i] = src[i];
        }
        __syncthreads();

        // ---- o1 = relu(h @ w3 + b3)  (N = 512, K = 1024) ----
        for (int nb = 0; nb < H2; nb += 128) {
            const int cb = nb + ct * 2;
            ull acc[8];
            {
                ull c0 = pk2(b3[cb], b3[cb + 1]);
                #pragma unroll
                for (int e = 0; e < 8; ++e) acc[e] = c0;
            }
            const ull* pw = w3u + (cb >> 1);
            for (int k0 = 0; k0 < HIDD; k0 += 4) {
                float4 hv[8];
                #pragma unroll
                for (int e = 0; e < 8; ++e)
                    hv[e] = *(const float4*)(hs + (e0l + e) * HIDD + k0);
                #pragma unroll
                for (int kk = 0; kk < 4; ++kk) {
                    ull b = __ldg(pw); pw += H2 / 2;
                    #pragma unroll
                    for (int e = 0; e < 8; ++e) {
                        float a = kk == 0 ? hv[e].x : kk == 1 ? hv[e].y
                                : kk == 2 ? hv[e].z : hv[e].w;
                        ull aa = pk2(a, a);
                        FMA2(acc[e], aa, b);
                    }
                }
            }
            #pragma unroll
            for (int e = 0; e < 8; ++e) {
                float2 v = upk2(acc[e]);
                float2 ov;
                ov.x = fmaxf(v.x, 0.0f);
                ov.y = fmaxf(v.y, 0.0f);
                *(float2*)(o1s + (e0l + e) * O1STR + cb) = ov;
            }
        }
        __syncthreads();

        // ---- o = tanh(o1 @ w4 + b4); emit output; update carried state ----
        if (tid < MENV * 2) {
            const int e = tid >> 1, c = tid & 1;
            float acc = b4[c];
            #pragma unroll 8
            for (int k = 0; k < H2; ++k)
                acc = fmaf(o1s[e * O1STR + k], __ldg(w4 + k * 2 + c), acc);
            float o = tanhf(acc);
            out[((size_t)(env0 + e) * SEQL + t) * 2 + c] = o;
            sts[tid] = o;
        }
        __syncthreads();
    }

    // ---- final hidden state ----
    if (write_h) {
        float* hout = out + OUTS_ELEMS;
        const float4* src = (const float4*)hs;
        float4* dst = (float4*)(hout + (size_t)env0 * HIDD);
        for (int i = tid; i < MENV * HIDD / 4; i += NTHR) dst[i] = src[i];
    }
}

extern "C" void kernel_launch(void* const* d_in, const int* in_sizes, int n_in,
                              void* d_out, int out_size) {
    const float* z    = (const float*)d_in[0];
    const float* hxs  = (const float*)d_in[1];
    const float* w1   = (const float*)d_in[2];
    const float* b1   = (const float*)d_in[3];
    const float* w2   = (const float*)d_in[4];
    const float* b2   = (const float*)d_in[5];
    const float* wih  = (const float*)d_in[6];
    const float* bih  = (const float*)d_in[7];
    const float* whh  = (const float*)d_in[8];
    const float* bhh  = (const float*)d_in[9];
    const float* w3   = (const float*)d_in[10];
    const float* b3   = (const float*)d_in[11];
    const float* w4   = (const float*)d_in[12];
    const float* b4   = (const float*)d_in[13];
    float* out = (float*)d_out;

    const int write_h = (out_size >= OUTS_ELEMS + NENVS * HIDD) ? 1 : 0;

    cudaFuncSetAttribute(gru_decoder_kernel,
                         cudaFuncAttributeMaxDynamicSharedMemorySize, SMEM_BYTES);

    gru_decoder_kernel<<<NCTA, NTHR, SMEM_BYTES>>>(
        z, hxs, w1, b1, w2, b2, wih, bih, whh, bhh, w3, b3, w4, b4,
        out, write_h);
}

// round 11
// speedup vs baseline: 1.1694x; 1.1694x over previous
#include <cuda_runtime.h>

// ---------------- problem constants ----------------
#define NENVS 4096
#define SEQL  128
#define LATD  64
#define EMBD  256
#define HIDD  1024
#define G3    3072          // 3 * HIDD
#define H2    512           // HIDD / 2
#define MENV  32            // envs per CTA
#define NCTA  (NENVS / MENV)
#define NTHR  512

#define OUTS_ELEMS (NENVS * SEQL * 2)

// ---------------- shared memory layout (floats) ----------------
#define SM_H   0                         // h       [32][1024]      32768
#define SM_U   (MENV * HIDD)             // union region base
#define SM_X2  SM_U                      // x2      [32][256]        8192
#define SM_X1  (SM_U + MENV * EMBD)      // x1      [32][32]         1024
#define SM_Z   (SM_X1 + MENV * 32)       // z_t     [32][64]         2048
#define SM_O1  SM_U                      // o1      [32][516] (overlays x1/x2/z)
#define O1STR  516                       // padded stride (bank-conflict avoidance)
#define SM_ST  (SM_U + MENV * O1STR)     // state   [32][2]
#define SM_TOT (SM_ST + MENV * 2)
#define SMEM_BYTES (SM_TOT * 4)

typedef unsigned long long ull;

// h_new scratch: can't overwrite smem h while it is still the K-operand
__device__ float g_hnew[NENVS * HIDD];

// ---------------- f32x2 helpers (PTX-only FFMA2 path on sm_103a) ----------------
__device__ __forceinline__ ull pk2(float lo, float hi) {
    ull r; asm("mov.b64 %0, {%1,%2};" : "=l"(r) : "f"(lo), "f"(hi)); return r;
}
__device__ __forceinline__ float2 upk2(ull v) {
    float2 f; asm("mov.b64 {%0,%1}, %2;" : "=f"(f.x), "=f"(f.y) : "l"(v)); return f;
}
#define FMA2(acc, aa, bb) \
    asm("fma.rn.f32x2 %0, %1, %2, %0;" : "+l"(acc) : "l"(aa), "l"(bb))

__device__ __forceinline__ float sigmf(float x) { return 1.0f / (1.0f + expf(-x)); }
__device__ __forceinline__ float gru1(float rr, float zz, float ni, float nh, float hold) {
    float r = sigmf(rr);
    float u = sigmf(zz);
    float n = tanhf(ni + r * nh);
    return (1.0f - u) * n + u * hold;
}

__global__ __launch_bounds__(NTHR, 1)
void gru_decoder_kernel(
    const float* __restrict__ z,   const float* __restrict__ h0,
    const float* __restrict__ w1,  const float* __restrict__ b1,
    const float* __restrict__ w2,  const float* __restrict__ b2,
    const float* __restrict__ wih, const float* __restrict__ bih,
    const float* __restrict__ whh, const float* __restrict__ bhh,
    const float* __restrict__ w3,  const float* __restrict__ b3,
    const float* __restrict__ w4,  const float* __restrict__ b4,
    float* __restrict__ out, int write_h)
{
    extern __shared__ float sm[];
    const int tid  = threadIdx.x;
    const int env0 = blockIdx.x * MENV;

    float* hs  = sm + SM_H;
    float* x2s = sm + SM_X2;
    float* x1s = sm + SM_X1;
    float* zs  = sm + SM_Z;
    float* o1s = sm + SM_O1;
    float* sts = sm + SM_ST;

    // initial hidden state: this CTA's 32 env rows are contiguous in h0
    {
        const float4* src = (const float4*)(h0 + (size_t)env0 * HIDD);
        float4* dst = (float4*)hs;
        for (int i = tid; i < MENV * HIDD / 4; i += NTHR) dst[i] = src[i];
    }
    if (tid < MENV * 2) sts[tid] = -2.0f;   // initial fake state/action
    __syncthreads();

    // gate/o1-loop tiling: 128 col-threads x 2 cols (256-col nb tiles),
    //                      4 env-groups x 8 envs
    const int ct  = tid & 127;
    const int mt  = tid >> 7;
    const int e0l = mt * 8;

    // x2-layer tiling: 256 col-threads, 2 env-halves of 16
    const int xc  = tid & 255;
    const int xe0 = (tid >> 8) * 16;

    const ull* wihu = (const ull*)wih;   // ull i <-> floats 2i, 2i+1
    const ull* whhu = (const ull*)whh;
    const ull* w3u  = (const ull*)w3;

    for (int t = 0; t < SEQL; ++t) {
        // ---- stage z_t into smem ----
        for (int i = tid; i < MENV * LATD; i += NTHR) {
            int e = i >> 6, d = i & 63;
            zs[i] = z[((size_t)(env0 + e) * SEQL + t) * LATD + d];
        }
        __syncthreads();

        // ---- x1 = relu([state | z_t] @ w1 + b1)  (K=66, N=32) ----
        for (int o = tid; o < MENV * 32; o += NTHR) {
            int e = o >> 5, c = o & 31;
            float acc = b1[c]
                      + sts[e * 2 + 0] * w1[c]
                      + sts[e * 2 + 1] * w1[32 + c];
            #pragma unroll 8
            for (int k = 0; k < LATD; ++k)
                acc = fmaf(zs[e * LATD + k], w1[(2 + k) * 32 + c], acc);
            x1s[e * 32 + c] = fmaxf(acc, 0.0f);
        }
        __syncthreads();

        // ---- x2 = relu(x1 @ w2 + b2)  (one column, 16 envs per thread) ----
        {
            float acc[16];
            #pragma unroll
            for (int e = 0; e < 16; ++e) acc[e] = b2[xc];
            #pragma unroll 4
            for (int k = 0; k < 32; ++k) {
                float b = __ldg(w2 + k * EMBD + xc);
                #pragma unroll
                for (int e = 0; e < 16; ++e)
                    acc[e] = fmaf(x1s[(xe0 + e) * 32 + k], b, acc[e]);
            }
            #pragma unroll
            for (int e = 0; e < 16; ++e)
                x2s[(xe0 + e) * EMBD + xc] = fmaxf(acc[e], 0.0f);
        }
        __syncthreads();

        // ---- fused GRU gates: per 256-col block compute
        //      (i_r+h_r), (i_z+h_z), i_n, h_n  then combine -> h_new ----
        for (int nb = 0; nb < HIDD; nb += 256) {
            const int cb = nb + ct * 2;            // 2 cols per thread
            ull aR[8], aZ[8], aNi[8], aNh[8];
            {
                ull r0 = pk2(bih[cb] + bhh[cb], bih[cb + 1] + bhh[cb + 1]);
                ull z0 = pk2(bih[HIDD + cb] + bhh[HIDD + cb],
                             bih[HIDD + cb + 1] + bhh[HIDD + cb + 1]);
                ull i0 = pk2(bih[2 * HIDD + cb], bih[2 * HIDD + cb + 1]);
                ull n0 = pk2(bhh[2 * HIDD + cb], bhh[2 * HIDD + cb + 1]);
                #pragma unroll
                for (int i = 0; i < 8; ++i) {
                    aR[i] = r0; aZ[i] = z0; aNi[i] = i0; aNh[i] = n0;
                }
            }
            // x2 @ wih   (K = 256), k-pairs with LDS.64 broadcast staging
            {
                const ull* pr = wihu + (cb >> 1);
                const ull* pz = wihu + ((HIDD + cb) >> 1);
                const ull* pn = wihu + ((2 * HIDD + cb) >> 1);
                for (int k0 = 0; k0 < EMBD; k0 += 2) {
                    float2 xv[8];
                    #pragma unroll
                    for (int e = 0; e < 8; ++e)
                        xv[e] = *(const float2*)(x2s + (e0l + e) * EMBD + k0);
                    #pragma unroll
                    for (int kk = 0; kk < 2; ++kk) {
                        ull br = __ldg(pr); pr += G3 / 2;
                        ull bz = __ldg(pz); pz += G3 / 2;
                        ull bn = __ldg(pn); pn += G3 / 2;
                        #pragma unroll
                        for (int e = 0; e < 8; ++e) {
                            float a = kk == 0 ? xv[e].x : xv[e].y;
                            ull aa = pk2(a, a);
                            FMA2(aR[e],  aa, br);
                            FMA2(aZ[e],  aa, bz);
                            FMA2(aNi[e], aa, bn);
                        }
                    }
                }
            }
            // h @ whh   (K = 1024)
            {
                const ull* pr = whhu + (cb >> 1);
                const ull* pz = whhu + ((HIDD + cb) >> 1);
                const ull* pn = whhu + ((2 * HIDD + cb) >> 1);
                for (int k0 = 0; k0 < HIDD; k0 += 2) {
                    float2 hv[8];
                    #pragma unroll
                    for (int e = 0; e < 8; ++e)
                        hv[e] = *(const float2*)(hs + (e0l + e) * HIDD + k0);
                    #pragma unroll
                    for (int kk = 0; kk < 2; ++kk) {
                        ull br = __ldg(pr); pr += G3 / 2;
                        ull bz = __ldg(pz); pz += G3 / 2;
                        ull bn = __ldg(pn); pn += G3 / 2;
                        #pragma unroll
                        for (int e = 0; e < 8; ++e) {
                            float a = kk == 0 ? hv[e].x : hv[e].y;
                            ull aa = pk2(a, a);
                            FMA2(aR[e],  aa, br);
                            FMA2(aZ[e],  aa, bz);
                            FMA2(aNh[e], aa, bn);
                        }
                    }
                }
            }
            // combine -> h_new (to global scratch; smem h still the K-operand)
            #pragma unroll
            for (int e = 0; e < 8; ++e) {
                float2 R = upk2(aR[e]);
                float2 Z = upk2(aZ[e]);
                float2 I = upk2(aNi[e]);
                float2 N = upk2(aNh[e]);
                const float* hrow = hs + (e0l + e) * HIDD + cb;
                float2 hv;
                hv.x = gru1(R.x, Z.x, I.x, N.x, hrow[0]);
                hv.y = gru1(R.y, Z.y, I.y, N.y, hrow[1]);
                *(float2*)(g_hnew + (size_t)(env0 + e0l + e) * HIDD + cb) = hv;
            }
        }
        __syncthreads();

        // ---- h <- h_new ----
        {
            const float4* src = (const float4*)(g_hnew + (size_t)env0 * HIDD);
            float4* dst = (float4*)hs;
            for (int i = tid; i < MENV * HIDD / 4; i += NTHR) dst[i] = src[i];
        }
        __syncthreads();

        // ---- o1 = relu(h @ w3 + b3)  (N = 512, K = 1024) ----
        for (int nb = 0; nb < H2; nb += 256) {
            const int cb = nb + ct * 2;
            ull acc[8];
            {
                ull c0 = pk2(b3[cb], b3[cb + 1]);
                #pragma unroll
                for (int e = 0; e < 8; ++e) acc[e] = c0;
            }
            const ull* pw = w3u + (cb >> 1);
            for (int k0 = 0; k0 < HIDD; k0 += 2) {
                float2 hv[8];
                #pragma unroll
                for (int e = 0; e < 8; ++e)
                    hv[e] = *(const float2*)(hs + (e0l + e) * HIDD + k0);
                #pragma unroll
                for (int kk = 0; kk < 2; ++kk) {
                    ull b = __ldg(pw); pw += H2 / 2;
                    #pragma unroll
                    for (int e = 0; e < 8; ++e) {
                        float a = kk == 0 ? hv[e].x : hv[e].y;
                        ull aa = pk2(a, a);
                        FMA2(acc[e], aa, b);
                    }
                }
            }
            #pragma unroll
            for (int e = 0; e < 8; ++e) {
                float2 v = upk2(acc[e]);
                float2 ov;
                ov.x = fmaxf(v.x, 0.0f);
                ov.y = fmaxf(v.y, 0.0f);
                *(float2*)(o1s + (e0l + e) * O1STR + cb) = ov;
            }
        }
        __syncthreads();

        // ---- o = tanh(o1 @ w4 + b4); emit output; update carried state ----
        if (tid < MENV * 2) {
            const int e = tid >> 1, c = tid & 1;
            float acc = b4[c];
            #pragma unroll 8
            for (int k = 0; k < H2; ++k)
                acc = fmaf(o1s[e * O1STR + k], __ldg(w4 + k * 2 + c), acc);
            float o = tanhf(acc);
            out[((size_t)(env0 + e) * SEQL + t) * 2 + c] = o;
            sts[tid] = o;
        }
        __syncthreads();
    }

    // ---- final hidden state ----
    if (write_h) {
        float* hout = out + OUTS_ELEMS;
        const float4* src = (const float4*)hs;
        float4* dst = (float4*)(hout + (size_t)env0 * HIDD);
        for (int i = tid; i < MENV * HIDD / 4; i += NTHR) dst[i] = src[i];
    }
}

extern "C" void kernel_launch(void* const* d_in, const int* in_sizes, int n_in,
                              void* d_out, int out_size) {
    const float* z    = (const float*)d_in[0];
    const float* hxs  = (const float*)d_in[1];
    const float* w1   = (const float*)d_in[2];
    const float* b1   = (const float*)d_in[3];
    const float* w2   = (const float*)d_in[4];
    const float* b2   = (const float*)d_in[5];
    const float* wih  = (const float*)d_in[6];
    const float* bih  = (const float*)d_in[7];
    const float* whh  = (const float*)d_in[8];
    const float* bhh  = (const float*)d_in[9];
    const float* w3   = (const float*)d_in[10];
    const float* b3   = (const float*)d_in[11];
    const float* w4   = (const float*)d_in[12];
    const float* b4   = (const float*)d_in[13];
    float* out = (float*)d_out;

    const int write_h = (out_size >= OUTS_ELEMS + NENVS * HIDD) ? 1 : 0;

    cudaFuncSetAttribute(gru_decoder_kernel,
                         cudaFuncAttributeMaxDynamicSharedMemorySize, SMEM_BYTES);

    gru_decoder_kernel<<<NCTA, NTHR, SMEM_BYTES>>>(
        z, hxs, w1, b1, w2, b2, wih, bih, whh, bhh, w3, b3, w4, b4,
        out, write_h);
}

// round 12
// speedup vs baseline: 1.1701x; 1.0006x over previous
#include <cuda_runtime.h>

// ---------------- problem constants ----------------
#define NENVS 4096
#define SEQL  128
#define LATD  64
#define EMBD  256
#define HIDD  1024
#define G3    3072          // 3 * HIDD
#define H2    512           // HIDD / 2
#define MENV  32            // envs per CTA
#define NCTA  (NENVS / MENV)
#define NTHR  512

#define OUTS_ELEMS (NENVS * SEQL * 2)

// ---------------- shared memory layout (floats) ----------------
#define SM_H   0                         // h       [32][1024]      32768
#define SM_U   (MENV * HIDD)             // union region base
#define SM_X2  SM_U                      // x2      [32][256]        8192
#define SM_X1  (SM_U + MENV * EMBD)      // x1      [32][32]         1024
#define SM_Z   (SM_X1 + MENV * 32)       // z_t     [32][64]         2048
#define SM_O1  SM_U                      // o1      [32][516] (overlays x1/x2/z)
#define O1STR  516                       // padded stride (bank-conflict avoidance)
#define SM_ST  (SM_U + MENV * O1STR)     // state   [32][2]
#define SM_TOT (SM_ST + MENV * 2)
#define SMEM_BYTES (SM_TOT * 4)

typedef unsigned long long ull;

// h_new scratch: can't overwrite smem h while it is still the K-operand
__device__ float g_hnew[NENVS * HIDD];

// ---------------- f32x2 helpers (PTX-only FFMA2 path on sm_103a) ----------------
__device__ __forceinline__ ull pk2(float lo, float hi) {
    ull r; asm("mov.b64 %0, {%1,%2};" : "=l"(r) : "f"(lo), "f"(hi)); return r;
}
__device__ __forceinline__ float2 upk2(ull v) {
    float2 f; asm("mov.b64 {%0,%1}, %2;" : "=f"(f.x), "=f"(f.y) : "l"(v)); return f;
}
#define FMA2(acc, aa, bb) \
    asm("fma.rn.f32x2 %0, %1, %2, %0;" : "+l"(acc) : "l"(aa), "l"(bb))

__device__ __forceinline__ float sigmf(float x) { return 1.0f / (1.0f + expf(-x)); }
__device__ __forceinline__ float gru1(float rr, float zz, float ni, float nh, float hold) {
    float r = sigmf(rr);
    float u = sigmf(zz);
    float n = tanhf(ni + r * nh);
    return (1.0f - u) * n + u * hold;
}

__global__ __launch_bounds__(NTHR, 1)
void gru_decoder_kernel(
    const float* __restrict__ z,   const float* __restrict__ h0,
    const float* __restrict__ w1,  const float* __restrict__ b1,
    const float* __restrict__ w2,  const float* __restrict__ b2,
    const float* __restrict__ wih, const float* __restrict__ bih,
    const float* __restrict__ whh, const float* __restrict__ bhh,
    const float* __restrict__ w3,  const float* __restrict__ b3,
    const float* __restrict__ w4,  const float* __restrict__ b4,
    float* __restrict__ out, int write_h)
{
    extern __shared__ float sm[];
    const int tid  = threadIdx.x;
    const int env0 = blockIdx.x * MENV;

    float* hs  = sm + SM_H;
    float* x2s = sm + SM_X2;
    float* x1s = sm + SM_X1;
    float* zs  = sm + SM_Z;
    float* o1s = sm + SM_O1;
    float* sts = sm + SM_ST;

    // initial hidden state: this CTA's 32 env rows are contiguous in h0
    {
        const float4* src = (const float4*)(h0 + (size_t)env0 * HIDD);
        float4* dst = (float4*)hs;
        for (int i = tid; i < MENV * HIDD / 4; i += NTHR) dst[i] = src[i];
    }
    if (tid < MENV * 2) sts[tid] = -2.0f;   // initial fake state/action
    __syncthreads();

    // gate/o1-loop tiling: 128 col-threads x 2 cols (256-col nb tiles),
    //                      4 env-groups x 8 envs
    const int ct  = tid & 127;
    const int mt  = tid >> 7;
    const int e0l = mt * 8;

    // x2-layer tiling: 256 col-threads, 2 env-halves of 16
    const int xc  = tid & 255;
    const int xe0 = (tid >> 8) * 16;

    const ull* wihu = (const ull*)wih;   // ull i <-> floats 2i, 2i+1
    const ull* whhu = (const ull*)whh;
    const ull* w3u  = (const ull*)w3;

    for (int t = 0; t < SEQL; ++t) {
        // ---- stage z_t into smem ----
        for (int i = tid; i < MENV * LATD; i += NTHR) {
            int e = i >> 6, d = i & 63;
            zs[i] = z[((size_t)(env0 + e) * SEQL + t) * LATD + d];
        }
        __syncthreads();

        // ---- x1 = relu([state | z_t] @ w1 + b1)  (K=66, N=32) ----
        for (int o = tid; o < MENV * 32; o += NTHR) {
            int e = o >> 5, c = o & 31;
            float acc = b1[c]
                      + sts[e * 2 + 0] * w1[c]
                      + sts[e * 2 + 1] * w1[32 + c];
            #pragma unroll 8
            for (int k = 0; k < LATD; ++k)
                acc = fmaf(zs[e * LATD + k], w1[(2 + k) * 32 + c], acc);
            x1s[e * 32 + c] = fmaxf(acc, 0.0f);
        }
        __syncthreads();

        // ---- x2 = relu(x1 @ w2 + b2)  (one column, 16 envs per thread) ----
        {
            float acc[16];
            #pragma unroll
            for (int e = 0; e < 16; ++e) acc[e] = b2[xc];
            #pragma unroll 4
            for (int k = 0; k < 32; ++k) {
                float b = __ldg(w2 + k * EMBD + xc);
                #pragma unroll
                for (int e = 0; e < 16; ++e)
                    acc[e] = fmaf(x1s[(xe0 + e) * 32 + k], b, acc[e]);
            }
            #pragma unroll
            for (int e = 0; e < 16; ++e)
                x2s[(xe0 + e) * EMBD + xc] = fmaxf(acc[e], 0.0f);
        }
        __syncthreads();

        // ---- fused GRU gates: per 256-col block compute
        //      (i_r+h_r), (i_z+h_z), i_n, h_n  then combine -> h_new ----
        for (int nb = 0; nb < HIDD; nb += 256) {
            const int cb = nb + ct * 2;            // 2 cols per thread
            ull aR[8], aZ[8], aNi[8], aNh[8];
            {
                ull r0 = pk2(bih[cb] + bhh[cb], bih[cb + 1] + bhh[cb + 1]);
                ull z0 = pk2(bih[HIDD + cb] + bhh[HIDD + cb],
                             bih[HIDD + cb + 1] + bhh[HIDD + cb + 1]);
                ull i0 = pk2(bih[2 * HIDD + cb], bih[2 * HIDD + cb + 1]);
                ull n0 = pk2(bhh[2 * HIDD + cb], bhh[2 * HIDD + cb + 1]);
                #pragma unroll
                for (int i = 0; i < 8; ++i) {
                    aR[i] = r0; aZ[i] = z0; aNi[i] = i0; aNh[i] = n0;
                }
            }
            // x2 @ wih   (K = 256), k-pairs with LDS.64 broadcast staging
            {
                const ull* pr = wihu + (cb >> 1);
                const ull* pz = wihu + ((HIDD + cb) >> 1);
                const ull* pn = wihu + ((2 * HIDD + cb) >> 1);
                for (int k0 = 0; k0 < EMBD; k0 += 2) {
                    float2 xv[8];
                    #pragma unroll
                    for (int e = 0; e < 8; ++e)
                        xv[e] = *(const float2*)(x2s + (e0l + e) * EMBD + k0);
                    #pragma unroll
                    for (int kk = 0; kk < 2; ++kk) {
                        ull br = __ldg(pr); pr += G3 / 2;
                        ull bz = __ldg(pz); pz += G3 / 2;
                        ull bn = __ldg(pn); pn += G3 / 2;
                        #pragma unroll
                        for (int e = 0; e < 8; ++e) {
                            float a = kk == 0 ? xv[e].x : xv[e].y;
                            ull aa = pk2(a, a);
                            FMA2(aR[e],  aa, br);
                            FMA2(aZ[e],  aa, bz);
                            FMA2(aNi[e], aa, bn);
                        }
                    }
                }
            }
            // h @ whh   (K = 1024)
            {
                const ull* pr = whhu + (cb >> 1);
                const ull* pz = whhu + ((HIDD + cb) >> 1);
                const ull* pn = whhu + ((2 * HIDD + cb) >> 1);
                for (int k0 = 0; k0 < HIDD; k0 += 2) {
                    float2 hv[8];
                    #pragma unroll
                    for (int e = 0; e < 8; ++e)
                        hv[e] = *(const float2*)(hs + (e0l + e) * HIDD + k0);
                    #pragma unroll
                    for (int kk = 0; kk < 2; ++kk) {
                        ull br = __ldg(pr); pr += G3 / 2;
                        ull bz = __ldg(pz); pz += G3 / 2;
                        ull bn = __ldg(pn); pn += G3 / 2;
                        #pragma unroll
                        for (int e = 0; e < 8; ++e) {
                            float a = kk == 0 ? hv[e].x : hv[e].y;
                            ull aa = pk2(a, a);
                            FMA2(aR[e],  aa, br);
                            FMA2(aZ[e],  aa, bz);
                            FMA2(aNh[e], aa, bn);
                        }
                    }
                }
            }
            // combine -> h_new (to global scratch; smem h still the K-operand)
            #pragma unroll
            for (int e = 0; e < 8; ++e) {
                float2 R = upk2(aR[e]);
                float2 Z = upk2(aZ[e]);
                float2 I = upk2(aNi[e]);
                float2 N = upk2(aNh[e]);
                const float* hrow = hs + (e0l + e) * HIDD + cb;
                float2 hv;
                hv.x = gru1(R.x, Z.x, I.x, N.x, hrow[0]);
                hv.y = gru1(R.y, Z.y, I.y, N.y, hrow[1]);
                *(float2*)(g_hnew + (size_t)(env0 + e0l + e) * HIDD + cb) = hv;
            }
        }
        __syncthreads();

        // ---- h <- h_new ----
        {
            const float4* src = (const float4*)(g_hnew + (size_t)env0 * HIDD);
            float4* dst = (float4*)hs;
            for (int i = tid; i < MENV * HIDD / 4; i += NTHR) dst[i] = src[i];
        }
        __syncthreads();

        // ---- o1 = relu(h @ w3 + b3)  (N = 512, K = 1024) ----
        for (int nb = 0; nb < H2; nb += 256) {
            const int cb = nb + ct * 2;
            ull acc[8];
            {
                ull c0 = pk2(b3[cb], b3[cb + 1]);
                #pragma unroll
                for (int e = 0; e < 8; ++e) acc[e] = c0;
            }
            const ull* pw = w3u + (cb >> 1);
            for (int k0 = 0; k0 < HIDD; k0 += 2) {
                float2 hv[8];
                #pragma unroll
                for (int e = 0; e < 8; ++e)
                    hv[e] = *(const float2*)(hs + (e0l + e) * HIDD + k0);
                #pragma unroll
                for (int kk = 0; kk < 2; ++kk) {
                    ull b = __ldg(pw); pw += H2 / 2;
                    #pragma unroll
                    for (int e = 0; e < 8; ++e) {
                        float a = kk == 0 ? hv[e].x : hv[e].y;
                        ull aa = pk2(a, a);
                        FMA2(acc[e], aa, b);
                    }
                }
            }
            #pragma unroll
            for (int e = 0; e < 8; ++e) {
                float2 v = upk2(acc[e]);
                float2 ov;
                ov.x = fmaxf(v.x, 0.0f);
                ov.y = fmaxf(v.y, 0.0f);
                *(float2*)(o1s + (e0l + e) * O1STR + cb) = ov;
            }
        }
        __syncthreads();

        // ---- o = tanh(o1 @ w4 + b4); emit output; update carried state ----
        if (tid < MENV * 2) {
            const int e = tid >> 1, c = tid & 1;
            float acc = b4[c];
            #pragma unroll 8
            for (int k = 0; k < H2; ++k)
                acc = fmaf(o1s[e * O1STR + k], __ldg(w4 + k * 2 + c), acc);
            float o = tanhf(acc);
            out[((size_t)(env0 + e) * SEQL + t) * 2 + c] = o;
            sts[tid] = o;
        }
        __syncthreads();
    }

    // ---- final hidden state ----
    if (write_h) {
        float* hout = out + OUTS_ELEMS;
        const float4* src = (const float4*)hs;
        float4* dst = (float4*)(hout + (size_t)env0 * HIDD);
        for (int i = tid; i < MENV * HIDD / 4; i += NTHR) dst[i] = src[i];
    }
}

extern "C" void kernel_launch(void* const* d_in, const int* in_sizes, int n_in,
                              void* d_out, int out_size) {
    const float* z    = (const float*)d_in[0];
    const float* hxs  = (const float*)d_in[1];
    const float* w1   = (const float*)d_in[2];
    const float* b1   = (const float*)d_in[3];
    const float* w2   = (const float*)d_in[4];
    const float* b2   = (const float*)d_in[5];
    const float* wih  = (const float*)d_in[6];
    const float* bih  = (const float*)d_in[7];
    const float* whh  = (const float*)d_in[8];
    const float* bhh  = (const float*)d_in[9];
    const float* w3   = (const float*)d_in[10];
    const float* b3   = (const float*)d_in[11];
    const float* w4   = (const float*)d_in[12];
    const float* b4   = (const float*)d_in[13];
    float* out = (float*)d_out;

    const int write_h = (out_size >= OUTS_ELEMS + NENVS * HIDD) ? 1 : 0;

    cudaFuncSetAttribute(gru_decoder_kernel,
                         cudaFuncAttributeMaxDynamicSharedMemorySize, SMEM_BYTES);

    gru_decoder_kernel<<<NCTA, NTHR, SMEM_BYTES>>>(
        z, hxs, w1, b1, w2, b2, wih, bih, whh, bhh, w3, b3, w4, b4,
        out, write_h);
}

// round 13
// speedup vs baseline: 1.5571x; 1.3307x over previous
#include <cuda_runtime.h>

// ---------------- problem constants ----------------
#define NENVS 4096
#define SEQL  128
#define LATD  64
#define EMBD  256
#define HIDD  1024
#define G3    3072          // 3 * HIDD
#define H2    512           // HIDD / 2
#define MENV  32            // envs per CTA
#define NCTA  (NENVS / MENV)
#define NTHR  512

#define OUTS_ELEMS (NENVS * SEQL * 2)

// ---------------- shared memory layout (floats) ----------------
#define SM_H   0                         // h       [32][1024]      32768
#define SM_U   (MENV * HIDD)             // union region base
#define SM_X2  SM_U                      // x2      [32][256]        8192
#define SM_X1  (SM_U + MENV * EMBD)      // x1      [32][32]         1024
#define SM_Z   (SM_X1 + MENV * 32)       // z_t     [32][64]         2048
#define SM_O1  SM_U                      // o1      [32][516] (overlays x1/x2/z)
#define O1STR  516                       // padded stride (bank-conflict avoidance)
#define SM_ST  (SM_U + MENV * O1STR)     // state   [32][2]
#define SM_TOT (SM_ST + MENV * 2)
#define SMEM_BYTES (SM_TOT * 4)

typedef unsigned long long ull;

// h_new scratch: can't overwrite smem h while it is still the K-operand
__device__ float g_hnew[NENVS * HIDD];

// ---------------- f32x2 helpers (PTX-only FFMA2 path on sm_103a) ----------------
__device__ __forceinline__ ull pk2(float lo, float hi) {
    ull r; asm("mov.b64 %0, {%1,%2};" : "=l"(r) : "f"(lo), "f"(hi)); return r;
}
__device__ __forceinline__ float2 upk2(ull v) {
    float2 f; asm("mov.b64 {%0,%1}, %2;" : "=f"(f.x), "=f"(f.y) : "l"(v)); return f;
}
#define FMA2(acc, aa, bb) \
    asm("fma.rn.f32x2 %0, %1, %2, %0;" : "+l"(acc) : "l"(aa), "l"(bb))

__device__ __forceinline__ float sigmf(float x) { return 1.0f / (1.0f + expf(-x)); }
__device__ __forceinline__ float gru1(float rr, float zz, float ni, float nh, float hold) {
    float r = sigmf(rr);
    float u = sigmf(zz);
    float n = tanhf(ni + r * nh);
    return (1.0f - u) * n + u * hold;
}

__global__ __launch_bounds__(NTHR, 1)
void gru_decoder_kernel(
    const float* __restrict__ z,   const float* __restrict__ h0,
    const float* __restrict__ w1,  const float* __restrict__ b1,
    const float* __restrict__ w2,  const float* __restrict__ b2,
    const float* __restrict__ wih, const float* __restrict__ bih,
    const float* __restrict__ whh, const float* __restrict__ bhh,
    const float* __restrict__ w3,  const float* __restrict__ b3,
    const float* __restrict__ w4,  const float* __restrict__ b4,
    float* __restrict__ out, int write_h)
{
    extern __shared__ float sm[];
    const int tid  = threadIdx.x;
    const int env0 = blockIdx.x * MENV;

    float* hs  = sm + SM_H;
    float* x2s = sm + SM_X2;
    float* x1s = sm + SM_X1;
    float* zs  = sm + SM_Z;
    float* o1s = sm + SM_O1;
    float* sts = sm + SM_ST;

    // initial hidden state: this CTA's 32 env rows are contiguous in h0
    {
        const float4* src = (const float4*)(h0 + (size_t)env0 * HIDD);
        float4* dst = (float4*)hs;
        for (int i = tid; i < MENV * HIDD / 4; i += NTHR) dst[i] = src[i];
    }
    if (tid < MENV * 2) sts[tid] = -2.0f;   // initial fake state/action
    __syncthreads();

    // gate/o1-loop tiling: 128 col-threads x 2 cols (256-col nb tiles),
    //                      4 env-groups x 8 envs
    const int ct  = tid & 127;
    const int mt  = tid >> 7;
    const int e0l = mt * 8;

    // x2-layer tiling: 256 col-threads, 2 env-halves of 16
    const int xc  = tid & 255;
    const int xe0 = (tid >> 8) * 16;

    const ull* wihu = (const ull*)wih;   // ull i <-> floats 2i, 2i+1
    const ull* whhu = (const ull*)whh;
    const ull* w3u  = (const ull*)w3;

    for (int t = 0; t < SEQL; ++t) {
        // ---- stage z_t into smem ----
        for (int i = tid; i < MENV * LATD; i += NTHR) {
            int e = i >> 6, d = i & 63;
            zs[i] = z[((size_t)(env0 + e) * SEQL + t) * LATD + d];
        }
        __syncthreads();

        // ---- x1 = relu([state | z_t] @ w1 + b1)  (K=66, N=32) ----
        for (int o = tid; o < MENV * 32; o += NTHR) {
            int e = o >> 5, c = o & 31;
            float acc = b1[c]
                      + sts[e * 2 + 0] * w1[c]
                      + sts[e * 2 + 1] * w1[32 + c];
            #pragma unroll 8
            for (int k = 0; k < LATD; ++k)
                acc = fmaf(zs[e * LATD + k], w1[(2 + k) * 32 + c], acc);
            x1s[e * 32 + c] = fmaxf(acc, 0.0f);
        }
        __syncthreads();

        // ---- x2 = relu(x1 @ w2 + b2)  (one column, 16 envs per thread) ----
        {
            float acc[16];
            #pragma unroll
            for (int e = 0; e < 16; ++e) acc[e] = b2[xc];
            #pragma unroll 4
            for (int k = 0; k < 32; ++k) {
                float b = __ldg(w2 + k * EMBD + xc);
                #pragma unroll
                for (int e = 0; e < 16; ++e)
                    acc[e] = fmaf(x1s[(xe0 + e) * 32 + k], b, acc[e]);
            }
            #pragma unroll
            for (int e = 0; e < 16; ++e)
                x2s[(xe0 + e) * EMBD + xc] = fmaxf(acc[e], 0.0f);
        }
        __syncthreads();

        // ---- fused GRU gates: per 256-col block compute
        //      (i_r+h_r), (i_z+h_z), i_n, h_n  then combine -> h_new ----
        for (int nb = 0; nb < HIDD; nb += 256) {
            const int cb = nb + ct * 2;            // 2 cols per thread
            ull aR[8], aZ[8], aNi[8], aNh[8];
            {
                ull r0 = pk2(bih[cb] + bhh[cb], bih[cb + 1] + bhh[cb + 1]);
                ull z0 = pk2(bih[HIDD + cb] + bhh[HIDD + cb],
                             bih[HIDD + cb + 1] + bhh[HIDD + cb + 1]);
                ull i0 = pk2(bih[2 * HIDD + cb], bih[2 * HIDD + cb + 1]);
                ull n0 = pk2(bhh[2 * HIDD + cb], bhh[2 * HIDD + cb + 1]);
                #pragma unroll
                for (int i = 0; i < 8; ++i) {
                    aR[i] = r0; aZ[i] = z0; aNi[i] = i0; aNh[i] = n0;
                }
            }

            // one k-pair of FMAs: weights (w0*,w1*) for k0 and k0+1
            auto pair_fma = [&](const float* act, int stride, int k0,
                                ull w0r, ull w0z, ull w0n,
                                ull w1r, ull w1z, ull w1n, ull* aN) {
                float2 xv[8];
                #pragma unroll
                for (int e = 0; e < 8; ++e)
                    xv[e] = *(const float2*)(act + (e0l + e) * stride + k0);
                #pragma unroll
                for (int e = 0; e < 8; ++e) {
                    ull aa = pk2(xv[e].x, xv[e].x);
                    FMA2(aR[e], aa, w0r);
                    FMA2(aZ[e], aa, w0z);
                    FMA2(aN[e], aa, w0n);
                }
                #pragma unroll
                for (int e = 0; e < 8; ++e) {
                    ull aa = pk2(xv[e].y, xv[e].y);
                    FMA2(aR[e], aa, w1r);
                    FMA2(aZ[e], aa, w1z);
                    FMA2(aN[e], aa, w1n);
                }
            };

            // software-pipelined 3-gate weight stream (prefetch depth: 1 pair)
            auto stream3 = [&](const ull* p0, int K,
                               const float* act, int stride, ull* aN) {
                const ull* pr = p0;
                const ull* pz = p0 + (HIDD >> 1);
                const ull* pn = p0 + HIDD;
                ull c0r = __ldg(pr),          c0z = __ldg(pz),          c0n = __ldg(pn);
                ull c1r = __ldg(pr + G3 / 2), c1z = __ldg(pz + G3 / 2), c1n = __ldg(pn + G3 / 2);
                pr += G3; pz += G3; pn += G3;
                int k0 = 0;
                for (; k0 < K - 2; k0 += 2) {
                    ull n0r = __ldg(pr),          n0z = __ldg(pz),          n0n = __ldg(pn);
                    ull n1r = __ldg(pr + G3 / 2), n1z = __ldg(pz + G3 / 2), n1n = __ldg(pn + G3 / 2);
                    pr += G3; pz += G3; pn += G3;
                    pair_fma(act, stride, k0, c0r, c0z, c0n, c1r, c1z, c1n, aN);
                    c0r = n0r; c0z = n0z; c0n = n0n;
                    c1r = n1r; c1z = n1z; c1n = n1n;
                }
                pair_fma(act, stride, k0, c0r, c0z, c0n, c1r, c1z, c1n, aN);
            };

            stream3(wihu + (cb >> 1), EMBD, x2s, EMBD, aNi);   // x2 @ wih
            stream3(whhu + (cb >> 1), HIDD, hs,  HIDD, aNh);   // h  @ whh

            // combine -> h_new (to global scratch; smem h still the K-operand)
            #pragma unroll
            for (int e = 0; e < 8; ++e) {
                float2 R = upk2(aR[e]);
                float2 Z = upk2(aZ[e]);
                float2 I = upk2(aNi[e]);
                float2 N = upk2(aNh[e]);
                const float* hrow = hs + (e0l + e) * HIDD + cb;
                float2 hv;
                hv.x = gru1(R.x, Z.x, I.x, N.x, hrow[0]);
                hv.y = gru1(R.y, Z.y, I.y, N.y, hrow[1]);
                *(float2*)(g_hnew + (size_t)(env0 + e0l + e) * HIDD + cb) = hv;
            }
        }
        __syncthreads();

        // ---- h <- h_new ----
        {
            const float4* src = (const float4*)(g_hnew + (size_t)env0 * HIDD);
            float4* dst = (float4*)hs;
            for (int i = tid; i < MENV * HIDD / 4; i += NTHR) dst[i] = src[i];
        }
        __syncthreads();

        // ---- o1 = relu(h @ w3 + b3)  (N = 512, K = 1024), pipelined ----
        for (int nb = 0; nb < H2; nb += 256) {
            const int cb = nb + ct * 2;
            ull acc[8];
            {
                ull c0 = pk2(b3[cb], b3[cb + 1]);
                #pragma unroll
                for (int e = 0; e < 8; ++e) acc[e] = c0;
            }

            auto o1_pair = [&](int k0, ull w0, ull w1) {
                float2 hv[8];
                #pragma unroll
                for (int e = 0; e < 8; ++e)
                    hv[e] = *(const float2*)(hs + (e0l + e) * HIDD + k0);
                #pragma unroll
                for (int e = 0; e < 8; ++e) {
                    ull aa = pk2(hv[e].x, hv[e].x);
                    FMA2(acc[e], aa, w0);
                }
                #pragma unroll
                for (int e = 0; e < 8; ++e) {
                    ull aa = pk2(hv[e].y, hv[e].y);
                    FMA2(acc[e], aa, w1);
                }
            };

            const ull* pw = w3u + (cb >> 1);
            ull c0 = __ldg(pw), c1 = __ldg(pw + H2 / 2);
            pw += H2;
            int k0 = 0;
            for (; k0 < HIDD - 2; k0 += 2) {
                ull n0 = __ldg(pw), n1 = __ldg(pw + H2 / 2);
                pw += H2;
                o1_pair(k0, c0, c1);
                c0 = n0; c1 = n1;
            }
            o1_pair(k0, c0, c1);

            #pragma unroll
            for (int e = 0; e < 8; ++e) {
                float2 v = upk2(acc[e]);
                float2 ov;
                ov.x = fmaxf(v.x, 0.0f);
                ov.y = fmaxf(v.y, 0.0f);
                *(float2*)(o1s + (e0l + e) * O1STR + cb) = ov;
            }
        }
        __syncthreads();

        // ---- o = tanh(o1 @ w4 + b4); emit output; update carried state ----
        if (tid < MENV * 2) {
            const int e = tid >> 1, c = tid & 1;
            float acc = b4[c];
            #pragma unroll 8
            for (int k = 0; k < H2; ++k)
                acc = fmaf(o1s[e * O1STR + k], __ldg(w4 + k * 2 + c), acc);
            float o = tanhf(acc);
            out[((size_t)(env0 + e) * SEQL + t) * 2 + c] = o;
            sts[tid] = o;
        }
        __syncthreads();
    }

    // ---- final hidden state ----
    if (write_h) {
        float* hout = out + OUTS_ELEMS;
        const float4* src = (const float4*)hs;
        float4* dst = (float4*)(hout + (size_t)env0 * HIDD);
        for (int i = tid; i < MENV * HIDD / 4; i += NTHR) dst[i] = src[i];
    }
}

extern "C" void kernel_launch(void* const* d_in, const int* in_sizes, int n_in,
                              void* d_out, int out_size) {
    const float* z    = (const float*)d_in[0];
    const float* hxs  = (const float*)d_in[1];
    const float* w1   = (const float*)d_in[2];
    const float* b1   = (const float*)d_in[3];
    const float* w2   = (const float*)d_in[4];
    const float* b2   = (const float*)d_in[5];
    const float* wih  = (const float*)d_in[6];
    const float* bih  = (const float*)d_in[7];
    const float* whh  = (const float*)d_in[8];
    const float* bhh  = (const float*)d_in[9];
    const float* w3   = (const float*)d_in[10];
    const float* b3   = (const float*)d_in[11];
    const float* w4   = (const float*)d_in[12];
    const float* b4   = (const float*)d_in[13];
    float* out = (float*)d_out;

    const int write_h = (out_size >= OUTS_ELEMS + NENVS * HIDD) ? 1 : 0;

    cudaFuncSetAttribute(gru_decoder_kernel,
                         cudaFuncAttributeMaxDynamicSharedMemorySize, SMEM_BYTES);

    gru_decoder_kernel<<<NCTA, NTHR, SMEM_BYTES>>>(
        z, hxs, w1, b1, w2, b2, wih, bih, whh, bhh, w3, b3, w4, b4,
        out, write_h);
}